// round 3
// baseline (speedup 1.0000x reference)
#include <cuda_runtime.h>
#include <cuda_bf16.h>
#include <cstdint>

// Soft VQ encoding, fused single kernel.
// X: (b, n, 128) fp32, C: (128, 128), S: (128,)  ->  E: (b, 128, 128)
//
// Per 64-row chunk:
//   GEMM1: XC[r,k] = sum_d X[r,d]*C[k,d]           (f32x2 packed FMA)
//   D[r,k] = S[k]*(X2[r] + C2[k] - 2*XC)
//   softmax over k (128) -> A[r,k]  (in shared)
//   GEMM2: E[k,d] += sum_r A[r,k]*X[r,d]           (register-resident E, f32x2)
// Per CTA: E and Asum accumulate over all its chunks of one batch; flush via
// atomicAdd with the -Asum[k]*C[k,d] correction folded in.

#define KDIM 128
#define DDIM 128
#define CHUNK 64
#define THREADS 256
#define GRID 152

// shared layout (floats)
#define CT_STRIDE   130           // Ct[d][k], k-major pairs readable as 64-bit
#define CT_FLOATS   (128*CT_STRIDE)            // 16640
#define XS_STRIDE   132
#define XS_FLOATS   (CHUNK*XS_STRIDE)          // 8448
#define AS_FLOATS   (CHUNK*XS_STRIDE)          // 8448
#define SMEM_FLOATS (CT_FLOATS + XS_FLOATS + AS_FLOATS + 64 + 128 + 128 + 128)
#define SMEM_BYTES  (SMEM_FLOATS * 4)          // 135936

typedef unsigned long long u64;

__device__ __forceinline__ u64 pack2(float lo, float hi) {
    u64 r;
    asm("mov.b64 %0, {%1, %2};" : "=l"(r) : "f"(lo), "f"(hi));
    return r;
}
__device__ __forceinline__ void unpack2(u64 v, float& lo, float& hi) {
    asm("mov.b64 {%0, %1}, %2;" : "=f"(lo), "=f"(hi) : "l"(v));
}
__device__ __forceinline__ void ffma2(u64& acc, u64 a, u64 b) {
    asm("fma.rn.f32x2 %0, %1, %2, %0;" : "+l"(acc) : "l"(a), "l"(b));
}

__global__ void __launch_bounds__(THREADS, 1)
vq_zero_kernel(float* out, int n) {
    int i = blockIdx.x * blockDim.x + threadIdx.x;
    if (i < n) out[i] = 0.0f;
}

__global__ void __launch_bounds__(THREADS, 1)
vq_encode_kernel(const float* __restrict__ Xg,
                 const float* __restrict__ Cg,
                 const float* __restrict__ Sg,
                 float* __restrict__ out,
                 int n, int b) {
    extern __shared__ float sm[];
    float* Ct    = sm;                       // [128][130]  C transposed: Ct[d*130 + k]
    float* Xs    = Ct + CT_FLOATS;           // [64][132]
    float* As    = Xs + XS_FLOATS;           // [64][132]
    float* X2s   = As + AS_FLOATS;           // [64]
    float* C2s   = X2s + 64;                 // [128]
    float* Ss    = C2s + 128;                // [128]
    float* AsumS = Ss + 128;                 // [128]
    const u64* Ct_u = (const u64*)Ct;        // [128][65] pair view

    const int tid = threadIdx.x;
    const int w   = tid >> 5, l = tid & 31;
    const int tr  = tid >> 4, tc = tid & 15;   // GEMM1 / GEMM2 tiling

    // ---- one-time init: transpose C, copy S, compute C2 ----
    for (int f = tid; f < KDIM * DDIM; f += THREADS) {
        int k = f >> 7, d = f & 127;
        Ct[d * CT_STRIDE + k] = Cg[f];
    }
    if (tid < KDIM) Ss[tid] = Sg[tid];
    __syncthreads();
    if (tid < KDIM) {
        float c2a = 0.f, c2b = 0.f;
        for (int d = 0; d < DDIM; d += 2) {
            float v0 = Ct[d * CT_STRIDE + tid];
            float v1 = Ct[(d + 1) * CT_STRIDE + tid];
            c2a = fmaf(v0, v0, c2a);
            c2b = fmaf(v1, v1, c2b);
        }
        C2s[tid] = c2a + c2b;
    }
    // (ordered before first use by the per-chunk __syncthreads below)

    // ---- accumulators ----
    u64 accE[8][4];                          // E[k = tr+16i][d = 2*(tc+16jp) .. +1]
    #pragma unroll
    for (int i = 0; i < 8; ++i)
        #pragma unroll
        for (int j = 0; j < 4; ++j) accE[i][j] = 0ull;
    float asum = 0.f;                        // threads < 128: Asum[k=tid]

    const int cpb   = n >> 6;                // chunks per batch
    const int total = b * cpb;
    const int g     = blockIdx.x;
    const int t0 = (int)(((long long)g       * total) / GRID);
    const int t1 = (int)(((long long)(g + 1) * total) / GRID);

    int cur_b = -1;
    for (int t = t0; t <= t1; ++t) {
        int bb = (t < t1) ? (t / cpb) : -2;  // sentinel forces final flush
        // ---- flush on batch change ----
        if (bb != cur_b) {
            if (cur_b >= 0) {
                __syncthreads();
                if (tid < KDIM) { AsumS[tid] = asum; asum = 0.f; }
                __syncthreads();
                #pragma unroll
                for (int i = 0; i < 8; ++i) {
                    int k = tr + 16 * i;
                    float ak = AsumS[k];
                    const float* crow = Cg + k * DDIM;
                    size_t obase = ((size_t)cur_b * KDIM + k) * DDIM;
                    #pragma unroll
                    for (int jp = 0; jp < 4; ++jp) {
                        int d0 = 2 * (tc + 16 * jp);
                        float e0, e1;
                        unpack2(accE[i][jp], e0, e1);
                        accE[i][jp] = 0ull;
                        float2 cv = *(const float2*)(crow + d0);
                        atomicAdd(&out[obase + d0],     e0 - ak * cv.x);
                        atomicAdd(&out[obase + d0 + 1], e1 - ak * cv.y);
                    }
                }
                __syncthreads();
            }
            cur_b = bb;
        }
        if (t >= t1) break;
        int c = t - cur_b * cpb;

        // ---- load X chunk (64 x 128), compute X2 per row ----
        const float* Xbase = Xg + ((size_t)cur_b * n + (size_t)c * CHUNK) * DDIM;
        #pragma unroll
        for (int it = 0; it < 8; ++it) {
            int r = w + 8 * it;              // whole warp loads one row
            float4 v = *(const float4*)(Xbase + (size_t)r * DDIM + l * 4);
            *(float4*)(Xs + r * XS_STRIDE + l * 4) = v;
            float ss = v.x * v.x + v.y * v.y + v.z * v.z + v.w * v.w;
            ss += __shfl_xor_sync(0xffffffffu, ss, 16);
            ss += __shfl_xor_sync(0xffffffffu, ss, 8);
            ss += __shfl_xor_sync(0xffffffffu, ss, 4);
            ss += __shfl_xor_sync(0xffffffffu, ss, 2);
            ss += __shfl_xor_sync(0xffffffffu, ss, 1);
            if (l == 0) X2s[r] = ss;
        }
        __syncthreads();

        // ---- GEMM1: XC (rows r = tr+16i, k-pairs p = tc+16jp) ----
        {
            u64 a1[4][4];
            #pragma unroll
            for (int i = 0; i < 4; ++i)
                #pragma unroll
                for (int j = 0; j < 4; ++j) a1[i][j] = 0ull;

            #pragma unroll 4
            for (int dd = 0; dd < DDIM; ++dd) {
                const u64* ctr = Ct_u + dd * (CT_STRIDE / 2);
                u64 c0 = ctr[tc];
                u64 c1 = ctr[tc + 16];
                u64 c2 = ctr[tc + 32];
                u64 c3 = ctr[tc + 48];
                #pragma unroll
                for (int i = 0; i < 4; ++i) {
                    float xv = Xs[(tr + 16 * i) * XS_STRIDE + dd];
                    u64 xd = pack2(xv, xv);
                    ffma2(a1[i][0], xd, c0);
                    ffma2(a1[i][1], xd, c1);
                    ffma2(a1[i][2], xd, c2);
                    ffma2(a1[i][3], xd, c3);
                }
            }
            // D = S[k]*(X2[r] + C2[k] - 2*XC) -> As
            #pragma unroll
            for (int i = 0; i < 4; ++i) {
                int r = tr + 16 * i;
                float x2 = X2s[r];
                #pragma unroll
                for (int jp = 0; jp < 4; ++jp) {
                    float lo, hi;
                    unpack2(a1[i][jp], lo, hi);
                    int k0 = 2 * (tc + 16 * jp);
                    float d0 = Ss[k0]     * (x2 + C2s[k0]     - 2.f * lo);
                    float d1 = Ss[k0 + 1] * (x2 + C2s[k0 + 1] - 2.f * hi);
                    *(float2*)(As + r * XS_STRIDE + k0) = make_float2(d0, d1);
                }
            }
        }
        __syncthreads();

        // ---- softmax over k: 4 threads per row, 32 k each ----
        {
            int r = tid >> 2, q = tid & 3;
            float* row = As + r * XS_STRIDE + q * 32;
            float v[32];
            float m = -3.4e38f;
            #pragma unroll
            for (int j = 0; j < 32; ++j) { v[j] = row[j]; m = fmaxf(m, v[j]); }
            m = fmaxf(m, __shfl_xor_sync(0xffffffffu, m, 1));
            m = fmaxf(m, __shfl_xor_sync(0xffffffffu, m, 2));
            float s0 = 0.f, s1 = 0.f;
            #pragma unroll
            for (int j = 0; j < 32; j += 2) {
                v[j]     = __expf(v[j]     - m);
                v[j + 1] = __expf(v[j + 1] - m);
                s0 += v[j]; s1 += v[j + 1];
            }
            float s = s0 + s1;
            s += __shfl_xor_sync(0xffffffffu, s, 1);
            s += __shfl_xor_sync(0xffffffffu, s, 2);
            float inv = __frcp_rn(s);
            #pragma unroll
            for (int j = 0; j < 32; ++j) row[j] = v[j] * inv;
        }
        __syncthreads();

        // ---- Asum[k] partial (threads < 128) ----
        if (tid < KDIM) {
            float a0 = 0.f, a1 = 0.f, a2 = 0.f, a3 = 0.f;
            #pragma unroll 4
            for (int rr = 0; rr < CHUNK; rr += 4) {
                a0 += As[(rr    ) * XS_STRIDE + tid];
                a1 += As[(rr + 1) * XS_STRIDE + tid];
                a2 += As[(rr + 2) * XS_STRIDE + tid];
                a3 += As[(rr + 3) * XS_STRIDE + tid];
            }
            asum += (a0 + a1) + (a2 + a3);
        }

        // ---- GEMM2: E[k,d] += A[n,k]*X[n,d] ----
        {
            const u64* Xs_u = (const u64*)Xs;
            #pragma unroll 2
            for (int nn = 0; nn < CHUNK; ++nn) {
                const float* arow = As + nn * XS_STRIDE;
                const u64*   xrow = Xs_u + nn * (XS_STRIDE / 2);
                u64 x0 = xrow[tc];
                u64 x1 = xrow[tc + 16];
                u64 x2 = xrow[tc + 32];
                u64 x3 = xrow[tc + 48];
                #pragma unroll
                for (int i = 0; i < 8; ++i) {
                    float a = arow[tr + 16 * i];
                    u64 ad = pack2(a, a);
                    ffma2(accE[i][0], ad, x0);
                    ffma2(accE[i][1], ad, x1);
                    ffma2(accE[i][2], ad, x2);
                    ffma2(accE[i][3], ad, x3);
                }
            }
        }
        __syncthreads();   // before next chunk overwrites Xs/As
    }
}

extern "C" void kernel_launch(void* const* d_in, const int* in_sizes, int n_in,
                              void* d_out, int out_size) {
    (void)n_in;
    const float* X = (const float*)d_in[0];
    const float* C = (const float*)d_in[1];
    const float* S = (const float*)d_in[2];
    float* out = (float*)d_out;

    int b = out_size / (KDIM * DDIM);            // 8
    if (b < 1) b = 1;
    long long rows = (long long)in_sizes[0] / DDIM;   // b*n
    int n = (int)(rows / b);                     // 16384

    cudaFuncSetAttribute(vq_encode_kernel,
                         cudaFuncAttributeMaxDynamicSharedMemorySize, SMEM_BYTES);

    int zgrid = (out_size + THREADS - 1) / THREADS;
    vq_zero_kernel<<<zgrid, THREADS>>>(out, out_size);
    vq_encode_kernel<<<GRID, THREADS, SMEM_BYTES>>>(X, C, S, out, n, b);
}

// round 4
// speedup vs baseline: 1.1332x; 1.1332x over previous
#include <cuda_runtime.h>
#include <cuda_bf16.h>
#include <cstdint>

// Soft VQ encoding, fused single kernel.
// X: (b, n, 128) fp32, C: (128, 128), S: (128,)  ->  E: (b, 128, 128)
//
// Per 128-row chunk:
//   GEMM1: XC[r,k] = sum_d X[r,d]*C[k,d]           (f32x2, R8xP4 per-thread tile)
//   D[r,k] = S[k]*(X2[r] + C2[k] - 2*XC)
//   softmax over k (128) -> A[r,k]  (in shared, bank-conflict-free swizzle)
//   GEMM2: E[k,d] += sum_r A[r,k]*X[r,d]           (register-resident E, f32x2)
// Per CTA: E and Asum accumulate over all its chunks of one batch; flush via
// atomicAdd with the -Asum[k]*C[k,d] correction folded in.

#define KDIM 128
#define DDIM 128
#define CHUNK 128
#define THREADS 256
#define GRID 152

// shared layout (floats)
#define CT_STRIDE   130           // Ct[d][k], k-major pairs readable as 64-bit
#define CT_FLOATS   (128*CT_STRIDE)            // 16640
#define XS_STRIDE   132
#define XS_FLOATS   (CHUNK*XS_STRIDE)          // 16896
#define AS_FLOATS   (CHUNK*XS_STRIDE)          // 16896
#define SMEM_FLOATS (CT_FLOATS + XS_FLOATS + AS_FLOATS + 128 + 128 + 128 + 128)
#define SMEM_BYTES  (SMEM_FLOATS * 4)          // 203776

typedef unsigned long long u64;

__device__ __forceinline__ u64 pack2(float lo, float hi) {
    u64 r;
    asm("mov.b64 %0, {%1, %2};" : "=l"(r) : "f"(lo), "f"(hi));
    return r;
}
__device__ __forceinline__ void unpack2(u64 v, float& lo, float& hi) {
    asm("mov.b64 {%0, %1}, %2;" : "=f"(lo), "=f"(hi) : "l"(v));
}
__device__ __forceinline__ void ffma2(u64& acc, u64 a, u64 b) {
    asm("fma.rn.f32x2 %0, %1, %2, %0;" : "+l"(acc) : "l"(a), "l"(b));
}

__global__ void __launch_bounds__(THREADS, 1)
vq_zero_kernel(float* out, int n) {
    int i = blockIdx.x * blockDim.x + threadIdx.x;
    if (i < n) out[i] = 0.0f;
}

__global__ void __launch_bounds__(THREADS, 1)
vq_encode_kernel(const float* __restrict__ Xg,
                 const float* __restrict__ Cg,
                 const float* __restrict__ Sg,
                 float* __restrict__ out,
                 int n, int b) {
    extern __shared__ float sm[];
    float* Ct    = sm;                       // [128][130]  C transposed: Ct[d*130 + k]
    float* Xs    = Ct + CT_FLOATS;           // [128][132]
    float* As    = Xs + XS_FLOATS;           // [128][132]
    float* X2s   = As + AS_FLOATS;           // [128]
    float* C2s   = X2s + 128;                // [128]
    float* Ss    = C2s + 128;                // [128]
    float* AsumS = Ss + 128;                 // [128]
    const u64* Ct_u = (const u64*)Ct;        // [128][65] pair view

    const int tid = threadIdx.x;
    const int w   = tid >> 5, l = tid & 31;
    const int tr  = tid >> 4, tc = tid & 15;   // GEMM1 / GEMM2 tiling

    // ---- one-time init: transpose C, copy S, compute C2 ----
    for (int f = tid; f < KDIM * DDIM; f += THREADS) {
        int k = f >> 7, d = f & 127;
        Ct[d * CT_STRIDE + k] = Cg[f];
    }
    if (tid < KDIM) Ss[tid] = Sg[tid];
    __syncthreads();
    if (tid < KDIM) {
        float c2a = 0.f, c2b = 0.f;
        for (int d = 0; d < DDIM; d += 2) {
            float v0 = Ct[d * CT_STRIDE + tid];
            float v1 = Ct[(d + 1) * CT_STRIDE + tid];
            c2a = fmaf(v0, v0, c2a);
            c2b = fmaf(v1, v1, c2b);
        }
        C2s[tid] = c2a + c2b;
    }
    // (ordered before first use by the per-chunk __syncthreads below)

    // ---- accumulators ----
    u64 accE[8][4];                          // E[k = tr+16i][d = 2*(tc+16jp) .. +1]
    #pragma unroll
    for (int i = 0; i < 8; ++i)
        #pragma unroll
        for (int j = 0; j < 4; ++j) accE[i][j] = 0ull;
    float asum = 0.f;                        // threads < 128: Asum[k=tid]

    const int cpb   = n >> 7;                // chunks per batch
    const int total = b * cpb;
    const int g     = blockIdx.x;
    const int t0 = (int)(((long long)g       * total) / GRID);
    const int t1 = (int)(((long long)(g + 1) * total) / GRID);

    int cur_b = -1;
    for (int t = t0; t <= t1; ++t) {
        int bb = (t < t1) ? (t / cpb) : -2;  // sentinel forces final flush
        // ---- flush on batch change ----
        if (bb != cur_b) {
            if (cur_b >= 0) {
                __syncthreads();
                if (tid < KDIM) { AsumS[tid] = asum; asum = 0.f; }
                __syncthreads();
                #pragma unroll
                for (int i = 0; i < 8; ++i) {
                    int k = tr + 16 * i;
                    float ak = AsumS[k];
                    const float* crow = Cg + k * DDIM;
                    size_t obase = ((size_t)cur_b * KDIM + k) * DDIM;
                    #pragma unroll
                    for (int jp = 0; jp < 4; ++jp) {
                        int d0 = 2 * (tc + 16 * jp);
                        float e0, e1;
                        unpack2(accE[i][jp], e0, e1);
                        accE[i][jp] = 0ull;
                        float2 cv = *(const float2*)(crow + d0);
                        atomicAdd(&out[obase + d0],     e0 - ak * cv.x);
                        atomicAdd(&out[obase + d0 + 1], e1 - ak * cv.y);
                    }
                }
                __syncthreads();
            }
            cur_b = bb;
        }
        if (t >= t1) break;
        int c = t - cur_b * cpb;

        // ---- load X chunk (128 x 128), compute X2 per row ----
        const float* Xbase = Xg + ((size_t)cur_b * n + (size_t)c * CHUNK) * DDIM;
        #pragma unroll
        for (int it = 0; it < 16; ++it) {
            int r = w + 8 * it;              // whole warp loads one row
            float4 v = *(const float4*)(Xbase + (size_t)r * DDIM + l * 4);
            *(float4*)(Xs + r * XS_STRIDE + l * 4) = v;
            float ss = v.x * v.x + v.y * v.y + v.z * v.z + v.w * v.w;
            ss += __shfl_xor_sync(0xffffffffu, ss, 16);
            ss += __shfl_xor_sync(0xffffffffu, ss, 8);
            ss += __shfl_xor_sync(0xffffffffu, ss, 4);
            ss += __shfl_xor_sync(0xffffffffu, ss, 2);
            ss += __shfl_xor_sync(0xffffffffu, ss, 1);
            if (l == 0) X2s[r] = ss;
        }
        __syncthreads();

        // ---- GEMM1: XC (rows r = tr+16i i<8, k-pairs p = tc+16jp jp<4) ----
        {
            u64 a1[8][4];
            #pragma unroll
            for (int i = 0; i < 8; ++i)
                #pragma unroll
                for (int j = 0; j < 4; ++j) a1[i][j] = 0ull;

            const float* xsb = Xs + tr * XS_STRIDE;
            #pragma unroll 2
            for (int dd = 0; dd < DDIM; ++dd) {
                const u64* ctr = Ct_u + dd * (CT_STRIDE / 2);
                u64 c0 = ctr[tc];
                u64 c1 = ctr[tc + 16];
                u64 c2 = ctr[tc + 32];
                u64 c3 = ctr[tc + 48];
                #pragma unroll
                for (int i = 0; i < 8; ++i) {
                    float xv = xsb[16 * i * XS_STRIDE + dd];
                    u64 xd = pack2(xv, xv);
                    ffma2(a1[i][0], xd, c0);
                    ffma2(a1[i][1], xd, c1);
                    ffma2(a1[i][2], xd, c2);
                    ffma2(a1[i][3], xd, c3);
                }
            }
            // D = S[k]*(X2[r] + C2[k] - 2*XC) -> As
            #pragma unroll
            for (int i = 0; i < 8; ++i) {
                int r = tr + 16 * i;
                float x2 = X2s[r];
                #pragma unroll
                for (int jp = 0; jp < 4; ++jp) {
                    float lo, hi;
                    unpack2(a1[i][jp], lo, hi);
                    int k0 = 2 * (tc + 16 * jp);
                    float d0 = Ss[k0]     * (x2 + C2s[k0]     - 2.f * lo);
                    float d1 = Ss[k0 + 1] * (x2 + C2s[k0 + 1] - 2.f * hi);
                    *(float2*)(As + r * XS_STRIDE + k0) = make_float2(d0, d1);
                }
            }
        }
        __syncthreads();

        // ---- softmax over k: 4 threads per row, 32 k each, 2 row-halves ----
        // Swizzled element order within each 32-wide segment makes the 32
        // lanes of a warp (8 rows x 4 segs) hit 32 distinct banks:
        // bank = (5r + 8q + j) mod 32, collision needs 5*dr == 8*dq (mod 32),
        // impossible for |dr|<8, |dq|<4.
        #pragma unroll
        for (int h = 0; h < 2; ++h) {
            int r = (tid >> 2) + (h << 6), q = tid & 3;
            float* row = As + r * XS_STRIDE + q * 32;
            const int rot = (8 * q + r) & 31;
            float v[32];
            float m = -3.4e38f;
            #pragma unroll
            for (int j = 0; j < 32; ++j) {
                v[j] = row[(j + rot) & 31];
                m = fmaxf(m, v[j]);
            }
            m = fmaxf(m, __shfl_xor_sync(0xffffffffu, m, 1));
            m = fmaxf(m, __shfl_xor_sync(0xffffffffu, m, 2));
            float s0 = 0.f, s1 = 0.f;
            #pragma unroll
            for (int j = 0; j < 32; j += 2) {
                v[j]     = __expf(v[j]     - m);
                v[j + 1] = __expf(v[j + 1] - m);
                s0 += v[j]; s1 += v[j + 1];
            }
            float s = s0 + s1;
            s += __shfl_xor_sync(0xffffffffu, s, 1);
            s += __shfl_xor_sync(0xffffffffu, s, 2);
            float inv = __frcp_rn(s);
            #pragma unroll
            for (int j = 0; j < 32; ++j) row[(j + rot) & 31] = v[j] * inv;
        }
        __syncthreads();

        // ---- Asum[k] partial (threads < 128) ----
        if (tid < KDIM) {
            float a0 = 0.f, a1 = 0.f, a2 = 0.f, a3 = 0.f;
            #pragma unroll 4
            for (int rr = 0; rr < CHUNK; rr += 4) {
                a0 += As[(rr    ) * XS_STRIDE + tid];
                a1 += As[(rr + 1) * XS_STRIDE + tid];
                a2 += As[(rr + 2) * XS_STRIDE + tid];
                a3 += As[(rr + 3) * XS_STRIDE + tid];
            }
            asum += (a0 + a1) + (a2 + a3);
        }

        // ---- GEMM2: E[k,d] += A[n,k]*X[n,d] ----
        {
            const u64* Xs_u = (const u64*)Xs;
            #pragma unroll 2
            for (int nn = 0; nn < CHUNK; ++nn) {
                const float* arow = As + nn * XS_STRIDE;
                const u64*   xrow = Xs_u + nn * (XS_STRIDE / 2);
                u64 x0 = xrow[tc];
                u64 x1 = xrow[tc + 16];
                u64 x2 = xrow[tc + 32];
                u64 x3 = xrow[tc + 48];
                #pragma unroll
                for (int i = 0; i < 8; ++i) {
                    float a = arow[tr + 16 * i];
                    u64 ad = pack2(a, a);
                    ffma2(accE[i][0], ad, x0);
                    ffma2(accE[i][1], ad, x1);
                    ffma2(accE[i][2], ad, x2);
                    ffma2(accE[i][3], ad, x3);
                }
            }
        }
        __syncthreads();   // before next chunk overwrites Xs/As
    }
}

extern "C" void kernel_launch(void* const* d_in, const int* in_sizes, int n_in,
                              void* d_out, int out_size) {
    (void)n_in;
    const float* X = (const float*)d_in[0];
    const float* C = (const float*)d_in[1];
    const float* S = (const float*)d_in[2];
    float* out = (float*)d_out;

    int b = out_size / (KDIM * DDIM);            // 8
    if (b < 1) b = 1;
    long long rows = (long long)in_sizes[0] / DDIM;   // b*n
    int n = (int)(rows / b);                     // 16384

    cudaFuncSetAttribute(vq_encode_kernel,
                         cudaFuncAttributeMaxDynamicSharedMemorySize, SMEM_BYTES);

    int zgrid = (out_size + THREADS - 1) / THREADS;
    vq_zero_kernel<<<zgrid, THREADS>>>(out, out_size);
    vq_encode_kernel<<<GRID, THREADS, SMEM_BYTES>>>(X, C, S, out, n, b);
}